// round 17
// baseline (speedup 1.0000x reference)
#include <cuda_runtime.h>

// LinearDynamicalSystem: y[t] = b0*u[t] + b1*u[t-1] - f1*y[t-1] - f2*y[t-2]
// Two-level chunked scan, 3 kernels (NO inter-block sync, no atomics):
//   pass1:   per (chunk,tile) aggregate c = sum_k M^(L-1-k) e1 v[k]  (Horner)
//   combine: per column, sequential fold over chunks:
//              g_S[j] = s;  s = A s + c_j        (A = M^L by squaring)
//   pass2:   per (chunk,tile) exact replay from g_S, writes y.
//
// R15 post-mortem: in-kernel decoupled lookback at 256 chunks is O(nchunk^2)
// (~540 MB fold traffic, L1=42.7%, 93us). Two-level scan removes it:
// combine is linear (8 MB), pass1/pass2 are pure streaming.
//
// Inputs (metadata order):
//   d_in[0] b_coeff (2,) f32
//   d_in[1] f_coeff (2,) f32
//   d_in[2] u_in    (N, B) f32, row-major
//   d_in[3] y_init  (B, 2) f32  -> [y[-1], y[-2]]
//   d_in[4] u_init  (B, 1) f32  -> [u[-1]]
// Output: (N, B) f32

#define CHUNK_L   32
#define LOG2_L    5
#define TPB       128            // threads per block (pass1/pass2)
#define VEC       4              // batch columns per thread (float4)
#define TILE_B    (TPB * VEC)    // 512 batch columns per tile
#define MAX_CHUNK 256
#define MAX_B     2048

static_assert(CHUNK_L == (1 << LOG2_L), "CHUNK_L must be 2^LOG2_L");

// Scratch (static device arrays — no allocation).
__device__ float2 g_C[MAX_CHUNK * MAX_B];   // per-chunk aggregate (per column)
__device__ float2 g_S[MAX_CHUNK * MAX_B];   // per-chunk start state (per column)

// ---------------------------------------------------------------------------
// A = M^L by repeated squaring. Identical fmaf sequence everywhere.
__device__ __forceinline__ void mpow(float f1, float f2,
                                     float& a11, float& a12,
                                     float& a21, float& a22)
{
    float m11 = -f1, m12 = -f2, m21 = 1.f, m22 = 0.f;
#pragma unroll
    for (int it = 0; it < LOG2_L; ++it) {
        const float t11 = fmaf(m11, m11, m12 * m21);
        const float t12 = fmaf(m11, m12, m12 * m22);
        const float t21 = fmaf(m21, m11, m22 * m21);
        const float t22 = fmaf(m21, m12, m22 * m22);
        m11 = t11; m12 = t12; m21 = t21; m22 = t22;
    }
    a11 = m11; a12 = m12; a21 = m21; a22 = m22;
}

// ---------------------------------------------------------------------------
// Pass 1: chunk aggregates. grid = (nchunk * ntile), chunk-major.
template <int B_CT>
__global__ void __launch_bounds__(TPB) lds_pass1(
    const float* __restrict__ u,
    const float* __restrict__ u_init,
    const float* __restrict__ bc,
    const float* __restrict__ fc,
    int B_rt, int ntile)
{
    const int B     = (B_CT > 0) ? B_CT : B_rt;
    const int tid   = threadIdx.x;
    const int chunk = blockIdx.x / ntile;
    const int tile  = blockIdx.x % ntile;
    const int gb    = tile * TILE_B + tid * VEC;

    const float b0 = bc[0], b1 = bc[1];
    const float f1 = fc[0], f2 = fc[1];

    const int rowstride = B / VEC;
    const float4* __restrict__ up =
        (const float4*)(u) + (long)chunk * CHUNK_L * rowstride + (gb / VEC);

    float4 u_prev0;
    if (chunk == 0) u_prev0 = *(const float4*)(u_init + gb);
    else            u_prev0 = up[-rowstride];

    float4 c1 = make_float4(0.f, 0.f, 0.f, 0.f);
    float4 c2 = make_float4(0.f, 0.f, 0.f, 0.f);
    {
        float4 upv = u_prev0;
#pragma unroll 8
        for (int k = 0; k < CHUNK_L; ++k) {
            const float4 ut = up[k * rowstride];
            {
                const float v = fmaf(b0, ut.x, b1 * upv.x);
                const float n = fmaf(-f1, c1.x, fmaf(-f2, c2.x, v));
                c2.x = c1.x; c1.x = n;
            }
            {
                const float v = fmaf(b0, ut.y, b1 * upv.y);
                const float n = fmaf(-f1, c1.y, fmaf(-f2, c2.y, v));
                c2.y = c1.y; c1.y = n;
            }
            {
                const float v = fmaf(b0, ut.z, b1 * upv.z);
                const float n = fmaf(-f1, c1.z, fmaf(-f2, c2.z, v));
                c2.z = c1.z; c1.z = n;
            }
            {
                const float v = fmaf(b0, ut.w, b1 * upv.w);
                const float n = fmaf(-f1, c1.w, fmaf(-f2, c2.w, v));
                c2.w = c1.w; c1.w = n;
            }
            upv = ut;
        }
    }

    // Store aggregates: interleaved (c1,c2) per column = 2 float4 per thread.
    float4* dst = (float4*)&g_C[chunk * B + gb];
    dst[0] = make_float4(c1.x, c2.x, c1.y, c2.y);
    dst[1] = make_float4(c1.z, c2.z, c1.w, c2.w);
}

// ---------------------------------------------------------------------------
// Combine: one thread per batch column; sequential fold over chunks.
template <int B_CT>
__global__ void __launch_bounds__(256) lds_combine(
    const float* __restrict__ y_init,
    const float* __restrict__ fc,
    int B_rt, int nchunk)
{
    const int B = (B_CT > 0) ? B_CT : B_rt;
    const int b = blockIdx.x * blockDim.x + threadIdx.x;
    if (b >= B) return;

    const float f1 = fc[0], f2 = fc[1];
    float a11, a12, a21, a22;
    mpow(f1, f2, a11, a12, a21, a22);

    const float2 q = *(const float2*)(y_init + 2 * b);
    float sx = q.x, sy = q.y;

#pragma unroll 4
    for (int j = 0; j < nchunk; ++j) {
        g_S[j * B + b] = make_float2(sx, sy);
        const float2 c = g_C[j * B + b];
        const float nx = fmaf(a11, sx, fmaf(a12, sy, c.x));
        const float ny = fmaf(a21, sx, fmaf(a22, sy, c.y));
        sx = nx; sy = ny;
    }
}

// ---------------------------------------------------------------------------
// Pass 2: exact replay from known start state. u re-read is L2-resident.
template <int B_CT>
__global__ void __launch_bounds__(TPB) lds_pass2(
    const float* __restrict__ u,
    const float* __restrict__ u_init,
    const float* __restrict__ bc,
    const float* __restrict__ fc,
    float* __restrict__ out,
    int B_rt, int ntile)
{
    const int B     = (B_CT > 0) ? B_CT : B_rt;
    const int tid   = threadIdx.x;
    const int chunk = blockIdx.x / ntile;
    const int tile  = blockIdx.x % ntile;
    const int gb    = tile * TILE_B + tid * VEC;

    const float b0 = bc[0], b1 = bc[1];
    const float f1 = fc[0], f2 = fc[1];

    const int rowstride = B / VEC;
    const float4* __restrict__ up =
        (const float4*)(u) + (long)chunk * CHUNK_L * rowstride + (gb / VEC);
    float4* op = (float4*)(out) + (long)chunk * CHUNK_L * rowstride + (gb / VEC);

    float4 u_prev0;
    if (chunk == 0) u_prev0 = *(const float4*)(u_init + gb);
    else            u_prev0 = __ldcs(up - rowstride);

    // Start states for the VEC columns: 4 float2 = 2 float4.
    const float4* src = (const float4*)&g_S[chunk * B + gb];
    const float4 p0 = src[0];
    const float4 p1 = src[1];
    float y1x = p0.x, y2x = p0.y, y1y = p0.z, y2y = p0.w;
    float y1z = p1.x, y2z = p1.y, y1w = p1.z, y2w = p1.w;

    {
        float4 upv = u_prev0;
#pragma unroll 8
        for (int k = 0; k < CHUNK_L; ++k) {
            const float4 ut = __ldcs(up + k * rowstride);
            float4 yo;
            {
                const float v = fmaf(b0, ut.x, b1 * upv.x);
                yo.x = fmaf(-f1, y1x, fmaf(-f2, y2x, v));
                y2x = y1x; y1x = yo.x;
            }
            {
                const float v = fmaf(b0, ut.y, b1 * upv.y);
                yo.y = fmaf(-f1, y1y, fmaf(-f2, y2y, v));
                y2y = y1y; y1y = yo.y;
            }
            {
                const float v = fmaf(b0, ut.z, b1 * upv.z);
                yo.z = fmaf(-f1, y1z, fmaf(-f2, y2z, v));
                y2z = y1z; y1z = yo.z;
            }
            {
                const float v = fmaf(b0, ut.w, b1 * upv.w);
                yo.w = fmaf(-f1, y1w, fmaf(-f2, y2w, v));
                y2w = y1w; y1w = yo.w;
            }
            __stcs(op + k * rowstride, yo);
            upv = ut;
        }
    }
}

// ---------------------------------------------------------------------------
extern "C" void kernel_launch(void* const* d_in, const int* in_sizes, int n_in,
                              void* d_out, int out_size)
{
    const float* bc     = (const float*)d_in[0];
    const float* fc     = (const float*)d_in[1];
    const float* u      = (const float*)d_in[2];
    const float* y_init = (const float*)d_in[3];
    const float* u_init = (const float*)d_in[4];
    float* out = (float*)d_out;

    const int B      = in_sizes[3] / 2;      // y_init is (B, 2)
    const int N      = in_sizes[2] / B;      // u_in is (N, B)
    const int nchunk = N / CHUNK_L;          // 8192/32 = 256
    const int ntile  = B / TILE_B;           // 2048/512 = 4
    const int grid   = nchunk * ntile;       // 1024

    if (B == 2048) {
        lds_pass1<2048><<<grid, TPB>>>(u, u_init, bc, fc, B, ntile);
        lds_combine<2048><<<(B + 255) / 256, 256>>>(y_init, fc, B, nchunk);
        lds_pass2<2048><<<grid, TPB>>>(u, u_init, bc, fc, out, B, ntile);
    } else {
        lds_pass1<0><<<grid, TPB>>>(u, u_init, bc, fc, B, ntile);
        lds_combine<0><<<(B + 255) / 256, 256>>>(y_init, fc, B, nchunk);
        lds_pass2<0><<<grid, TPB>>>(u, u_init, bc, fc, out, B, ntile);
    }
}